// round 10
// baseline (speedup 1.0000x reference)
#include <cuda_runtime.h>
#include <math_constants.h>

// ---------------------------------------------------------------------------
// Quanv 3x3 layer, fully fused single kernel (112 blocks x 256 threads).
//
// Math: the circuit's entangling graph is a tree rooted at qubit 0; every
// qubit controls exactly one gate after all gates targeting it. Each
// controlled gate (c,t) is a qubit channel on t's 2x2 reduced density matrix
// rho = [[r0, wr+i*wi],[wr-i*wi, 1-r0]]:
//   r0' = lerp(r0, Cx*r0 + (1-Cx)/2 + Sx*(Sz*wr - Cz*wi), p1)
//   wr' = lerp(wr, Cz*wr + Sz*wi,                          p1)
//   wi' = lerp(wi, Cx*(Cz*wi - Sz*wr) + Sx*(r0 - 0.5),     p1)
// with p1 = control's |1> population. Encoding RX(2*pi*a - pi) on |0>:
//   r0 = (1 - cos 2pi a)/2, wr = 0, wi = -sin(2pi a)/2 ; leaf p1 = (1+cos)/2.
// Output feature = final r0 of qubit 0.
//
// Tiling: one block per (image b, output-row pair ih): 8*14 = 112 blocks
// (single wave), 256 threads. Disjoint pre-barrier roles:
//   t in [0,120)   : 120 pixel trig pairs (4x30 input strip) -> smem
//   t in [128,160) : 32 gate-constant float4s -> smem
//   t in [192,256) : (ih==0 only) zero 116 border pixels, 2 each
// Phase 2: 224 threads = (2 rows x 4 ch x 28 cols), one 8-channel chain each
// (shortest per-thread dependency chain; ILP across threads, not within).
// MUFU __sinf/__cosf throughout (args bounded, err ~1e-6 << 1e-3 gate).
// ---------------------------------------------------------------------------

__global__ void __launch_bounds__(256) quanv_fused(const float* __restrict__ x,
                                                   const float* __restrict__ qp,
                                                   float* __restrict__ out) {
    __shared__ float2 pixs[120];  // (cos 2pi a, sin 2pi a), rows i0..i0+3 x 30
    __shared__ float4 gs[32];     // per (channel, gate): Cz, Sz, Cx, Sx

    int blk = blockIdx.x;
    int b  = blk / 14;
    int ih = blk - b * 14;
    int i0 = ih * 2;              // first of the two output rows
    int t  = threadIdx.x;

    if (t < 120) {
        // ---- pixel strip trig ----
        int dr = t / 30;
        int c  = t - dr * 30;
        const float* px = x + (((b * 30) + i0 + dr) * 30 + c) * 3;
        float a = (px[0] + px[1] + px[2]) * (1.0f / 3.0f);
        float ang = 2.0f * CUDART_PI_F * a;
        pixs[t] = make_float2(__cosf(ang), __sinf(ang));
    } else if (t >= 128 && t < 160) {
        // ---- gate constants ----
        int e = t - 128;                  // e = ch*8 + k
        int ch = e >> 3, k = e & 7;
        float tz = qp[ch * 16 + 2 * k];
        float tx = qp[ch * 16 + 2 * k + 1];
        gs[e] = make_float4(__cosf(tz), __sinf(tz), __cosf(tx), __sinf(tx));
    } else if (t >= 192 && ih == 0) {
        // ---- border zeroing: 64 threads, up to 2 of 116 border px each ----
        int e0 = t - 192;
#pragma unroll
        for (int rep = 0; rep < 2; rep++) {
            int e = e0 + rep * 64;
            if (e < 116) {
                int r, c;
                if      (e < 30) { r = 0;          c = e;      }
                else if (e < 60) { r = 29;         c = e - 30; }
                else if (e < 88) { r = e - 60 + 1; c = 0;      }
                else             { r = e - 88 + 1; c = 29;     }
                ((float4*)out)[b * 900 + r * 30 + c] =
                    make_float4(0.f, 0.f, 0.f, 0.f);
            }
        }
    }

    __syncthreads();

    // ---- Phase 2: one thread per (row, channel, column). ----
    if (t >= 224) return;
    int rw  = t / 112;            // 0 or 1 -> output row i0+rw
    int rem = t - rw * 112;
    int ch  = rem / 28;
    int j   = rem - ch * 28;

    float cs[9], sn[9];
#pragma unroll
    for (int q = 0; q < 9; q++) {
        float2 v = pixs[(rw + q / 3) * 30 + j + (q % 3)];
        cs[q] = v.x; sn[q] = v.y;
    }

    float4 G0 = gs[ch * 8 + 0], G1 = gs[ch * 8 + 1];
    float4 G2 = gs[ch * 8 + 2], G3 = gs[ch * 8 + 3];
    float4 G4 = gs[ch * 8 + 4], G5 = gs[ch * 8 + 5];
    float4 G6 = gs[ch * 8 + 6], G7 = gs[ch * 8 + 7];

    // Leaf-control populations and targeted-qubit initial states.
    float p1_1 = 0.5f * (1.0f + cs[1]);
    float p1_3 = 0.5f * (1.0f + cs[3]);
    float p1_5 = 0.5f * (1.0f + cs[5]);
    float p1_8 = 0.5f * (1.0f + cs[8]);

    float r0_0 = 0.5f * (1.0f - cs[0]), wr0 = 0.0f, wi0 = -0.5f * sn[0];
    float r0_4 = 0.5f * (1.0f - cs[4]), wr4 = 0.0f, wi4 = -0.5f * sn[4];

    auto chan_full = [](float p1, float4 g, float& r0, float& wr, float& wi) {
        float nr0 = fmaf(g.z, r0, 0.5f * (1.0f - g.z)) + g.w * fmaf(g.y, wr, -g.x * wi);
        float nwr = fmaf(g.x, wr, g.y * wi);
        float nwi = fmaf(g.z, fmaf(g.x, wi, -g.y * wr), g.w * (r0 - 0.5f));
        r0 = fmaf(p1, nr0 - r0, r0);
        wr = fmaf(p1, nwr - wr, wr);
        wi = fmaf(p1, nwi - wi, wi);
    };
    auto chan_r0 = [](float p1, float4 g, float r0, float wr, float wi) {
        float nr0 = fmaf(g.z, r0, 0.5f * (1.0f - g.z)) + g.w * fmaf(g.y, wr, -g.x * wi);
        return fmaf(p1, nr0 - r0, r0);
    };

    // Gate sequence (PAIRS order).
    chan_full(p1_1, G0, r0_0, wr0, wi0);                                        // (1,0)
    float r2 = chan_r0(p1_3, G1, 0.5f * (1.0f - cs[2]), 0.0f, -0.5f * sn[2]);   // (3,2)
    chan_full(1.0f - r2, G2, r0_0, wr0, wi0);                                   // (2,0)
    float r7 = chan_r0(p1_8, G3, 0.5f * (1.0f - cs[7]), 0.0f, -0.5f * sn[7]);   // (8,7)
    chan_full(p1_5, G4, r0_4, wr4, wi4);                                        // (5,4)
    float r6 = chan_r0(1.0f - r7, G5, 0.5f * (1.0f - cs[6]), 0.0f, -0.5f * sn[6]); // (7,6)
    float r4 = chan_r0(1.0f - r6, G6, r0_4, wr4, wi4);                          // (6,4)
    float rf = chan_r0(1.0f - r4, G7, r0_0, wr0, wi0);                          // (4,0)

    // Output (B, 30, 30, C), interior at (i0+rw+1, j+1).
    out[(((b * 30) + i0 + rw + 1) * 30 + (j + 1)) * 4 + ch] = rf;
}

// ----------------------------- launch --------------------------------------
extern "C" void kernel_launch(void* const* d_in, const int* in_sizes, int n_in,
                              void* d_out, int out_size) {
    const float* x  = (const float*)d_in[0];   // (8,30,30,3)
    const float* qp = (const float*)d_in[1];   // (4,16)
    float* out = (float*)d_out;                // (8,30,30,4)

    quanv_fused<<<112, 256>>>(x, qp, out);     // single wave, one graph node
}

// round 11
// speedup vs baseline: 1.0048x; 1.0048x over previous
#include <cuda_runtime.h>
#include <math_constants.h>

// ---------------------------------------------------------------------------
// Quanv 3x3 layer, fully fused single kernel (single-wave tiling).
// FINAL: best-measured configuration (6.37 us). Launch-overhead-bound:
// all pipes <3%, DRAM 0.2%; remaining time is launch + graph-replay floor.
//
// Math: the circuit's entangling graph is a tree rooted at qubit 0; every
// qubit controls exactly one gate after all gates targeting it. Each
// controlled gate (c,t) is a qubit channel on t's 2x2 reduced density matrix
// rho = [[r0, wr+i*wi],[wr-i*wi, 1-r0]]:
//   r0' = lerp(r0, Cx*r0 + (1-Cx)/2 + Sx*(Sz*wr - Cz*wi), p1)
//   wr' = lerp(wr, Cz*wr + Sz*wi,                          p1)
//   wi' = lerp(wi, Cx*(Cz*wi - Sz*wr) + Sx*(r0 - 0.5),     p1)
// with p1 = control's |1> population. Encoding RX(2*pi*a - pi) on |0>:
//   r0 = (1 - cos 2pi a)/2, wr = 0, wi = -sin(2pi a)/2 ; leaf p1 = (1+cos)/2.
// Output feature = final r0 of qubit 0.
//
// Tiling: one block per (image b, row-pair ih): 8*14 = 112 blocks (< 148 SMs
// -> ONE wave), 256 threads. Phase 1 (smem): 120 pixel trig pairs for the
// 4x30 input strip + 32 gate-constant float4s (MUFU __sinf/__cosf — args
// bounded by 2*pi, approx error ~1e-6 << 1e-3 gate). Phase 2: 224 threads
// (2 rows x 4 ch x 28 cols) run the 8-channel chain. ih==0 blocks also zero
// the 116 border pixels of their image (disjoint addresses -> race-free).
// ---------------------------------------------------------------------------

__global__ void __launch_bounds__(256) quanv_fused(const float* __restrict__ x,
                                                   const float* __restrict__ qp,
                                                   float* __restrict__ out) {
    __shared__ float2 pixs[120];  // (cos 2pi a, sin 2pi a), rows i0..i0+3 x 30
    __shared__ float4 gs[32];     // per (channel, gate): Cz, Sz, Cx, Sx

    int blk = blockIdx.x;
    int b  = blk / 14;
    int ih = blk - b * 14;
    int i0 = ih * 2;              // first of the two output rows
    int t  = threadIdx.x;

    // ---- Phase 1a: pixel strip trig (threads 0..119). ----
    if (t < 120) {
        int dr = t / 30;
        int c  = t - dr * 30;
        const float* px = x + (((b * 30) + i0 + dr) * 30 + c) * 3;
        float a = (px[0] + px[1] + px[2]) * (1.0f / 3.0f);
        float ang = 2.0f * CUDART_PI_F * a;
        pixs[t] = make_float2(__cosf(ang), __sinf(ang));
    } else if (t < 152) {
        // ---- Phase 1b: gate constants (threads 120..151 -> 32 gates). ----
        int e = t - 120;                  // e = ch*8 + k
        int ch = e >> 3, k = e & 7;
        float tz = qp[ch * 16 + 2 * k];
        float tx = qp[ch * 16 + 2 * k + 1];
        gs[e] = make_float4(__cosf(tz), __sinf(tz), __cosf(tx), __sinf(tx));
    }

    // ---- Border zeroing (ih==0 blocks; threads 140..255 -> 116 px). ----
    if (ih == 0 && t >= 140) {
        int e = t - 140;
        int r, c;
        if      (e < 30) { r = 0;          c = e;      }
        else if (e < 60) { r = 29;         c = e - 30; }
        else if (e < 88) { r = e - 60 + 1; c = 0;      }
        else             { r = e - 88 + 1; c = 29;     }
        ((float4*)out)[b * 900 + r * 30 + c] = make_float4(0.f, 0.f, 0.f, 0.f);
    }

    __syncthreads();

    // ---- Phase 2: one thread per (row, channel, column). ----
    if (t >= 224) return;
    int rw  = t / 112;            // 0 or 1 -> output row i0+rw
    int rem = t - rw * 112;
    int ch  = rem / 28;
    int j   = rem - ch * 28;

    float cs[9], sn[9];
#pragma unroll
    for (int q = 0; q < 9; q++) {
        float2 v = pixs[(rw + q / 3) * 30 + j + (q % 3)];
        cs[q] = v.x; sn[q] = v.y;
    }

    float4 G0 = gs[ch * 8 + 0], G1 = gs[ch * 8 + 1];
    float4 G2 = gs[ch * 8 + 2], G3 = gs[ch * 8 + 3];
    float4 G4 = gs[ch * 8 + 4], G5 = gs[ch * 8 + 5];
    float4 G6 = gs[ch * 8 + 6], G7 = gs[ch * 8 + 7];

    // Leaf-control populations and targeted-qubit initial states.
    float p1_1 = 0.5f * (1.0f + cs[1]);
    float p1_3 = 0.5f * (1.0f + cs[3]);
    float p1_5 = 0.5f * (1.0f + cs[5]);
    float p1_8 = 0.5f * (1.0f + cs[8]);

    float r0_0 = 0.5f * (1.0f - cs[0]), wr0 = 0.0f, wi0 = -0.5f * sn[0];
    float r0_4 = 0.5f * (1.0f - cs[4]), wr4 = 0.0f, wi4 = -0.5f * sn[4];

    auto chan_full = [](float p1, float4 g, float& r0, float& wr, float& wi) {
        float nr0 = fmaf(g.z, r0, 0.5f * (1.0f - g.z)) + g.w * fmaf(g.y, wr, -g.x * wi);
        float nwr = fmaf(g.x, wr, g.y * wi);
        float nwi = fmaf(g.z, fmaf(g.x, wi, -g.y * wr), g.w * (r0 - 0.5f));
        r0 = fmaf(p1, nr0 - r0, r0);
        wr = fmaf(p1, nwr - wr, wr);
        wi = fmaf(p1, nwi - wi, wi);
    };
    auto chan_r0 = [](float p1, float4 g, float r0, float wr, float wi) {
        float nr0 = fmaf(g.z, r0, 0.5f * (1.0f - g.z)) + g.w * fmaf(g.y, wr, -g.x * wi);
        return fmaf(p1, nr0 - r0, r0);
    };

    // Gate sequence (PAIRS order).
    chan_full(p1_1, G0, r0_0, wr0, wi0);                                        // (1,0)
    float r2 = chan_r0(p1_3, G1, 0.5f * (1.0f - cs[2]), 0.0f, -0.5f * sn[2]);   // (3,2)
    chan_full(1.0f - r2, G2, r0_0, wr0, wi0);                                   // (2,0)
    float r7 = chan_r0(p1_8, G3, 0.5f * (1.0f - cs[7]), 0.0f, -0.5f * sn[7]);   // (8,7)
    chan_full(p1_5, G4, r0_4, wr4, wi4);                                        // (5,4)
    float r6 = chan_r0(1.0f - r7, G5, 0.5f * (1.0f - cs[6]), 0.0f, -0.5f * sn[6]); // (7,6)
    float r4 = chan_r0(1.0f - r6, G6, r0_4, wr4, wi4);                          // (6,4)
    float rf = chan_r0(1.0f - r4, G7, r0_0, wr0, wi0);                          // (4,0)

    // Output (B, 30, 30, C), interior at (i0+rw+1, j+1).
    out[(((b * 30) + i0 + rw + 1) * 30 + (j + 1)) * 4 + ch] = rf;
}

// ----------------------------- launch --------------------------------------
extern "C" void kernel_launch(void* const* d_in, const int* in_sizes, int n_in,
                              void* d_out, int out_size) {
    const float* x  = (const float*)d_in[0];   // (8,30,30,3)
    const float* qp = (const float*)d_in[1];   // (4,16)
    float* out = (float*)d_out;                // (8,30,30,4)

    quanv_fused<<<112, 256>>>(x, qp, out);     // single wave, one graph node
}